// round 9
// baseline (speedup 1.0000x reference)
#include <cuda_runtime.h>
#include <cuda_bf16.h>
#include <cstdint>

// ============ compile-time Cl(3,0,1) blade algebra (blade order matches reference) ============
__host__ __device__ constexpr int pc4(int m){ return (m&1)+((m>>1)&1)+((m>>2)&1)+((m>>3)&1); }
__host__ __device__ constexpr int maskOf(int i){
  return i==0?0 : i==1?1 : i==2?2 : i==3?4 : i==4?8 : i==5?3 : i==6?5 : i==7?9 :
         i==8?6 : i==9?10 : i==10?12 : i==11?7 : i==12?11 : i==13?13 : i==14?14 : 15;
}
__host__ __device__ constexpr int idxOf(int m){
  return m==0?0 : m==1?1 : m==2?2 : m==4?3 : m==8?4 : m==3?5 : m==5?6 : m==9?7 :
         m==6?8 : m==10?9 : m==12?10 : m==7?11 : m==11?12 : m==13?13 : m==14?14 : 15;
}
// sign of e_A * e_B from reordering (metric +1 on shared elems handled by caller)
__host__ __device__ constexpr int sperm(int a, int b){
  int s = 0;
  for (int i = 0; i < 4; ++i) if ((b>>i)&1) s += pc4(a >> (i+1));
  return (s&1) ? -1 : 1;
}
__host__ __device__ constexpr int gradeOf(int j){ return pc4(maskOf(j)); }
__host__ __device__ constexpr int pairOf(int j){ return (maskOf(j)&1) ? idxOf(maskOf(j)^1) : -1; }
__host__ __device__ constexpr int gpS(int j,int k){
  return (maskOf(j)&maskOf(k)&1) ? 0 : sperm(maskOf(j),maskOf(k));
}
__host__ __device__ constexpr int gpR(int j,int k){ return idxOf(maskOf(j)^maskOf(k)); }
__host__ __device__ constexpr int jnS(int j,int k){
  int b = maskOf(j), c = maskOf(k);
  if ((b|c) != 15) return 0;
  return sperm(b^c, 15^(b^c)) * sperm(15^b, 15^c) * sperm(b, 15^b) * sperm(c, 15^c);
}
__host__ __device__ constexpr int jnR(int j,int k){ return idxOf(15^(maskOf(j)^maskOf(k))); }

// fully-unrolled bilinears: nested 16-deep template recursions (stay under nvcc's depth limit)
template<int J, int K>
__device__ __forceinline__ void gp_k(float (&ga)[16], const float (&L)[16], const float (&R)[16]){
  if constexpr (K < 16){
    constexpr int s = gpS(J,K), r = gpR(J,K);
    if constexpr (s ==  1) ga[r] = fmaf( L[J], R[K], ga[r]);
    if constexpr (s == -1) ga[r] = fmaf(-L[J], R[K], ga[r]);
    gp_k<J, K+1>(ga, L, R);
  }
}
template<int J>
__device__ __forceinline__ void gp_j(float (&ga)[16], const float (&L)[16], const float (&R)[16]){
  if constexpr (J < 16){
    gp_k<J, 0>(ga, L, R);
    gp_j<J+1>(ga, L, R);
  }
}
template<int J, int K>
__device__ __forceinline__ void jn_k(float (&ja)[16], const float (&L)[16], const float (&R)[16]){
  if constexpr (K < 16){
    constexpr int s = jnS(J,K), r = jnR(J,K);
    if constexpr (s ==  1) ja[r] = fmaf( L[J], R[K], ja[r]);
    if constexpr (s == -1) ja[r] = fmaf(-L[J], R[K], ja[r]);
    jn_k<J, K+1>(ja, L, R);
  }
}
template<int J>
__device__ __forceinline__ void jn_j(float (&ja)[16], const float (&L)[16], const float (&R)[16]){
  if constexpr (J < 16){
    jn_k<J, 0>(ja, L, R);
    jn_j<J+1>(ja, L, R);
  }
}
// one equi-linear step for one input channel: acc[j] += w9[g(j)]*x[j] (+ w9[4+g(j)]*x[j\e0])
__device__ __forceinline__ void equi_step(float (&acc)[16], const float (&xi)[16], const float* w9){
  #pragma unroll
  for (int j = 0; j < 16; ++j){
    const int g = gradeOf(j);
    acc[j] = fmaf(w9[g], xi[j], acc[j]);
    const int p = pairOf(j);
    if (p >= 0) acc[j] = fmaf(w9[4+g], xi[p], acc[j]);
  }
}
// load NQ float4 quads into a register array through a raw pointer
template<int NQ>
__device__ __forceinline__ void ldq(float* d, const float* p){
  #pragma unroll
  for (int q = 0; q < NQ; ++q){
    float4 v = *(const float4*)(p + 4*q);
    d[4*q]=v.x; d[4*q+1]=v.y; d[4*q+2]=v.z; d[4*q+3]=v.w;
  }
}

// ============ sizes / layout ============
#define NTOK        32768
#define TOK_PER_BLK 32
#define NBLK        (NTOK / TOK_PER_BLK)
#define THREADS     512
#define XS_STRIDE   516   // 512+4 pad: lane bank offset 4 -> conflict-free LDS.128
#define SS_STRIDE   65
#define SMEM_BYTES  ((TOK_PER_BLK*XS_STRIDE + TOK_PER_BLK*SS_STRIDE + TOK_PER_BLK)*4)

// ============ packed weights (written by prep kernel each launch) ============
__device__ float4 g_WLR[16][32][5];   // {wl[9], wr[9], pad2} per (hidden ch, in ch)
__device__ float4 g_WJ [16][32][5];   // {wjl[9], wjr[9], pad2}
__device__ float4 g_WS4[16][64];      // {wl_s, wr_s, wjl_s, wjr_s}
__device__ float4 g_WB [16][32][6];   // per warp w, hidden ch c: {wout[2w][9], wout[2w+1][9], mvs2s[4w..4w+3], pad2}
__device__ float4 g_WBS[16][64][2];   // per warp w, scalar s: {s2mv[2w], s2mv[2w+1], s2s[4w], s2s[4w+1]},{s2s[4w+2],s2s[4w+3],0,0}

__global__ void gb_prep(
    const float* __restrict__ wl_mv, const float* __restrict__ wl_s,
    const float* __restrict__ wr_mv, const float* __restrict__ wr_s,
    const float* __restrict__ wjl_mv, const float* __restrict__ wjl_s,
    const float* __restrict__ wjr_mv, const float* __restrict__ wjr_s,
    const float* __restrict__ wo_mv, const float* __restrict__ wo_s2mv,
    const float* __restrict__ wo_mvs2s, const float* __restrict__ wo_s2s)
{
  int tid = blockIdx.x * blockDim.x + threadIdx.x;
  if (tid < 16*32){
    int c = tid >> 5, i = tid & 31;
    float t[20]; t[18]=0.f; t[19]=0.f;
    for (int b = 0; b < 9; ++b){ t[b] = wl_mv[(c*32+i)*9+b]; t[9+b] = wr_mv[(c*32+i)*9+b]; }
    for (int q = 0; q < 5; ++q) g_WLR[c][i][q] = make_float4(t[4*q],t[4*q+1],t[4*q+2],t[4*q+3]);
    for (int b = 0; b < 9; ++b){ t[b] = wjl_mv[(c*32+i)*9+b]; t[9+b] = wjr_mv[(c*32+i)*9+b]; }
    for (int q = 0; q < 5; ++q) g_WJ[c][i][q] = make_float4(t[4*q],t[4*q+1],t[4*q+2],t[4*q+3]);
    int w = c, c2 = i;
    float u[24]; u[22]=0.f; u[23]=0.f;
    for (int b = 0; b < 9; ++b){
      u[b]   = wo_mv[((2*w  )*32 + c2)*9 + b];
      u[9+b] = wo_mv[((2*w+1)*32 + c2)*9 + b];
    }
    for (int q = 0; q < 4; ++q) u[18+q] = wo_mvs2s[(4*w+q)*32 + c2];
    for (int q = 0; q < 6; ++q) g_WB[w][c2][q] = make_float4(u[4*q],u[4*q+1],u[4*q+2],u[4*q+3]);
  }
  if (tid < 16*64){
    int c = tid >> 6, s = tid & 63;
    g_WS4[c][s] = make_float4(wl_s[c*64+s], wr_s[c*64+s], wjl_s[c*64+s], wjr_s[c*64+s]);
    int w = c;
    g_WBS[w][s][0] = make_float4(wo_s2mv[(2*w)*64+s], wo_s2mv[(2*w+1)*64+s],
                                 wo_s2s[(4*w+0)*64+s], wo_s2s[(4*w+1)*64+s]);
    g_WBS[w][s][1] = make_float4(wo_s2s[(4*w+2)*64+s], wo_s2s[(4*w+3)*64+s], 0.f, 0.f);
  }
}

// ============ main kernel ============
__global__ void __launch_bounds__(THREADS, 1) gb_main(
    const float* __restrict__ mv, const float* __restrict__ refmv,
    const float* __restrict__ sc, float* __restrict__ out_mv, float* __restrict__ out_s)
{
  extern __shared__ float sm[];
  float* xs   = sm;                              // [32][516]: x, reused for hidden
  float* ss   = sm + TOK_PER_BLK*XS_STRIDE;      // [32][65]
  float* refs = ss + TOK_PER_BLK*SS_STRIDE;      // [32]
  const int tid = threadIdx.x;
  const long long t0 = (long long)blockIdx.x * TOK_PER_BLK;

  // stage x: coalesced gmem -> padded token-major smem
  {
    const float4* gx = (const float4*)(mv + t0*512);
    #pragma unroll
    for (int r = 0; r < 8; ++r){
      int g4 = r*THREADS + tid;              // 4096 float4 per block
      int tok = g4 >> 7, f4 = g4 & 127;
      *(float4*)&xs[tok*XS_STRIDE + f4*4] = gx[g4];
    }
  }
  // stage scalars (scalar stores: stride 65 is odd)
  {
    float4 v = ((const float4*)(sc + t0*64))[tid];
    int tok = tid >> 4, s4 = tid & 15;
    float* p = &ss[tok*SS_STRIDE + s4*4];
    p[0]=v.x; p[1]=v.y; p[2]=v.z; p[3]=v.w;
  }
  if (tid < TOK_PER_BLK) refs[tid] = refmv[(t0+tid)*16 + 15];
  __syncthreads();

  const int w = tid >> 5, lane = tid & 31;
  const float* xrow = &xs[lane*XS_STRIDE];
  const long long gtok = t0 + lane;
  const float ref15 = refs[lane];

  // ---- scalar biases for the 4 first-stage equi-linears ----
  float bL=0.f, bR=0.f, bJL=0.f, bJR=0.f;
  #pragma unroll 8
  for (int s = 0; s < 64; ++s){
    float sv = ss[lane*SS_STRIDE + s];
    float4 wv = g_WS4[w][s];
    bL  = fmaf(wv.x, sv, bL);  bR  = fmaf(wv.y, sv, bR);
    bJL = fmaf(wv.z, sv, bJL); bJR = fmaf(wv.w, sv, bJR);
  }

  // ---- phase A pass 1: left/right -> geometric product ----
  float ga[16];
  {
    float L[16], R[16];
    #pragma unroll
    for (int j = 0; j < 16; ++j){ L[j]=0.f; R[j]=0.f; }
    L[0]=bL; R[0]=bR;
    #pragma unroll 4
    for (int i = 0; i < 32; ++i){
      float xi[16]; ldq<4>(xi, xrow + i*16);
      float wb[20]; ldq<5>(wb, (const float*)g_WLR[w][i]);
      equi_step(L, xi, wb);
      equi_step(R, xi, wb+9);
    }
    #pragma unroll
    for (int j = 0; j < 16; ++j) ga[j]=0.f;
    gp_j<0>(ga, L, R);
  }

  // ---- phase A pass 2: jl/jr -> join, scaled by reference_mv[...,15] ----
  float ja[16];
  {
    float L[16], R[16];
    #pragma unroll
    for (int j = 0; j < 16; ++j){ L[j]=0.f; R[j]=0.f; }
    L[0]=bJL; R[0]=bJR;
    #pragma unroll 4
    for (int i = 0; i < 32; ++i){
      float xi[16]; ldq<4>(xi, xrow + i*16);
      float wb[20]; ldq<5>(wb, (const float*)g_WJ[w][i]);
      equi_step(L, xi, wb);
      equi_step(R, xi, wb+9);
    }
    #pragma unroll
    for (int j = 0; j < 16; ++j) ja[j]=0.f;
    jn_j<0>(ja, L, R);
    #pragma unroll
    for (int j = 0; j < 16; ++j) ja[j] *= ref15;
  }

  // ---- write hidden back into xs (x is dead) ----
  __syncthreads();
  {
    float* hrow = &xs[lane*XS_STRIDE];
    #pragma unroll
    for (int q = 0; q < 4; ++q){
      *(float4*)(hrow +  w    *16 + 4*q) = make_float4(ga[4*q],ga[4*q+1],ga[4*q+2],ga[4*q+3]);
      *(float4*)(hrow + (16+w)*16 + 4*q) = make_float4(ja[4*q],ja[4*q+1],ja[4*q+2],ja[4*q+3]);
    }
  }
  __syncthreads();

  // ---- phase B: output equi-linear (ch 2w,2w+1) + out_s (ch 4w..4w+3) ----
  float b0=0.f, b1=0.f, os0=0.f, os1=0.f, os2=0.f, os3=0.f;
  #pragma unroll 8
  for (int s = 0; s < 64; ++s){
    float sv = ss[lane*SS_STRIDE + s];
    float4 u = g_WBS[w][s][0];
    float4 v = g_WBS[w][s][1];
    b0  = fmaf(u.x, sv, b0);  b1  = fmaf(u.y, sv, b1);
    os0 = fmaf(u.z, sv, os0); os1 = fmaf(u.w, sv, os1);
    os2 = fmaf(v.x, sv, os2); os3 = fmaf(v.y, sv, os3);
  }
  float A0[16], A1[16];
  #pragma unroll
  for (int j = 0; j < 16; ++j){ A0[j]=0.f; A1[j]=0.f; }
  A0[0]=b0; A1[0]=b1;
  const float* hrow = &xs[lane*XS_STRIDE];
  #pragma unroll 4
  for (int c = 0; c < 32; ++c){
    float hi[16]; ldq<4>(hi, hrow + c*16);
    float wb[24]; ldq<6>(wb, (const float*)g_WB[w][c]);
    equi_step(A0, hi, wb);
    equi_step(A1, hi, wb+9);
    os0 = fmaf(wb[18], hi[0], os0); os1 = fmaf(wb[19], hi[0], os1);
    os2 = fmaf(wb[20], hi[0], os2); os3 = fmaf(wb[21], hi[0], os3);
  }

  // ---- write outputs ----
  float* om = out_mv + (gtok*32 + 2*w)*16;
  #pragma unroll
  for (int q = 0; q < 4; ++q)
    ((float4*)om)[q]      = make_float4(A0[4*q],A0[4*q+1],A0[4*q+2],A0[4*q+3]);
  #pragma unroll
  for (int q = 0; q < 4; ++q)
    ((float4*)(om+16))[q] = make_float4(A1[4*q],A1[4*q+1],A1[4*q+2],A1[4*q+3]);
  *(float4*)(out_s + gtok*64 + 4*w) = make_float4(os0,os1,os2,os3);
}

// ============ launch ============
extern "C" void kernel_launch(void* const* d_in, const int* in_sizes, int n_in,
                              void* d_out, int out_size) {
  const float* mv    = (const float*)d_in[0];
  const float* refmv = (const float*)d_in[1];
  const float* sc    = (const float*)d_in[2];
  // d_in[3..5] = basis/gp/jn tables (folded at compile time)
  const float* wl_mv  = (const float*)d_in[6];
  const float* wl_s   = (const float*)d_in[7];
  const float* wr_mv  = (const float*)d_in[8];
  const float* wr_s   = (const float*)d_in[9];
  const float* wjl_mv = (const float*)d_in[10];
  const float* wjl_s  = (const float*)d_in[11];
  const float* wjr_mv = (const float*)d_in[12];
  const float* wjr_s  = (const float*)d_in[13];
  const float* wo_mv    = (const float*)d_in[14];
  const float* wo_s2mv  = (const float*)d_in[15];
  const float* wo_mvs2s = (const float*)d_in[16];
  const float* wo_s2s   = (const float*)d_in[17];

  float* out_mv = (float*)d_out;                       // (B,N,32,16)
  float* out_s  = out_mv + (long long)NTOK * 32 * 16;  // (B,N,64)

  gb_prep<<<2, 512>>>(wl_mv, wl_s, wr_mv, wr_s, wjl_mv, wjl_s, wjr_mv, wjr_s,
                      wo_mv, wo_s2mv, wo_mvs2s, wo_s2s);

  cudaFuncSetAttribute(gb_main, cudaFuncAttributeMaxDynamicSharedMemorySize, SMEM_BYTES);
  gb_main<<<NBLK, THREADS, SMEM_BYTES>>>(mv, refmv, sc, out_mv, out_s);
}

// round 11
// speedup vs baseline: 1.7484x; 1.7484x over previous
#include <cuda_runtime.h>
#include <cuda_bf16.h>
#include <cstdint>

// ============ compile-time Cl(3,0,1) blade algebra (blade order matches reference) ============
__host__ __device__ constexpr int pc4(int m){ return (m&1)+((m>>1)&1)+((m>>2)&1)+((m>>3)&1); }
__host__ __device__ constexpr int maskOf(int i){
  return i==0?0 : i==1?1 : i==2?2 : i==3?4 : i==4?8 : i==5?3 : i==6?5 : i==7?9 :
         i==8?6 : i==9?10 : i==10?12 : i==11?7 : i==12?11 : i==13?13 : i==14?14 : 15;
}
__host__ __device__ constexpr int idxOf(int m){
  return m==0?0 : m==1?1 : m==2?2 : m==4?3 : m==8?4 : m==3?5 : m==5?6 : m==9?7 :
         m==6?8 : m==10?9 : m==12?10 : m==7?11 : m==11?12 : m==13?13 : m==14?14 : 15;
}
__host__ __device__ constexpr int sperm(int a, int b){
  int s = 0;
  for (int i = 0; i < 4; ++i) if ((b>>i)&1) s += pc4(a >> (i+1));
  return (s&1) ? -1 : 1;
}
__host__ __device__ constexpr int gradeOf(int j){ return pc4(maskOf(j)); }
__host__ __device__ constexpr int pairOf(int j){ return (maskOf(j)&1) ? idxOf(maskOf(j)^1) : -1; }
__host__ __device__ constexpr int gpS(int j,int k){
  return (maskOf(j)&maskOf(k)&1) ? 0 : sperm(maskOf(j),maskOf(k));
}
__host__ __device__ constexpr int gpR(int j,int k){ return idxOf(maskOf(j)^maskOf(k)); }
__host__ __device__ constexpr int jnS(int j,int k){
  int b = maskOf(j), c = maskOf(k);
  if ((b|c) != 15) return 0;
  return sperm(b^c, 15^(b^c)) * sperm(15^b, 15^c) * sperm(b, 15^b) * sperm(c, 15^c);
}
__host__ __device__ constexpr int jnR(int j,int k){ return idxOf(15^(maskOf(j)^maskOf(k))); }

// fully-unrolled bilinears: nested 16-deep template recursions (under nvcc's depth limit)
template<int J, int K>
__device__ __forceinline__ void gp_k(float (&ga)[16], const float (&L)[16], const float (&R)[16]){
  if constexpr (K < 16){
    constexpr int s = gpS(J,K), r = gpR(J,K);
    if constexpr (s ==  1) ga[r] = fmaf( L[J], R[K], ga[r]);
    if constexpr (s == -1) ga[r] = fmaf(-L[J], R[K], ga[r]);
    gp_k<J, K+1>(ga, L, R);
  }
}
template<int J>
__device__ __forceinline__ void gp_j(float (&ga)[16], const float (&L)[16], const float (&R)[16]){
  if constexpr (J < 16){
    gp_k<J, 0>(ga, L, R);
    gp_j<J+1>(ga, L, R);
  }
}
template<int J, int K>
__device__ __forceinline__ void jn_k(float (&ja)[16], const float (&L)[16], const float (&R)[16]){
  if constexpr (K < 16){
    constexpr int s = jnS(J,K), r = jnR(J,K);
    if constexpr (s ==  1) ja[r] = fmaf( L[J], R[K], ja[r]);
    if constexpr (s == -1) ja[r] = fmaf(-L[J], R[K], ja[r]);
    jn_k<J, K+1>(ja, L, R);
  }
}
template<int J>
__device__ __forceinline__ void jn_j(float (&ja)[16], const float (&L)[16], const float (&R)[16]){
  if constexpr (J < 16){
    jn_k<J, 0>(ja, L, R);
    jn_j<J+1>(ja, L, R);
  }
}
// one equi-linear step for one input channel: acc[j] += w9[g(j)]*x[j] (+ w9[4+g(j)]*x[j\e0])
__device__ __forceinline__ void equi_step(float (&acc)[16], const float (&xi)[16], const float* w9){
  #pragma unroll
  for (int j = 0; j < 16; ++j){
    const int g = gradeOf(j);
    acc[j] = fmaf(w9[g], xi[j], acc[j]);
    const int p = pairOf(j);
    if (p >= 0) acc[j] = fmaf(w9[4+g], xi[p], acc[j]);
  }
}
// load NQ float4 quads into a register array through a raw pointer
template<int NQ>
__device__ __forceinline__ void ldq(float* d, const float* p){
  #pragma unroll
  for (int q = 0; q < NQ; ++q){
    float4 v = *(const float4*)(p + 4*q);
    d[4*q]=v.x; d[4*q+1]=v.y; d[4*q+2]=v.z; d[4*q+3]=v.w;
  }
}

// ============ sizes / layout ============
#define NTOK        32768
#define TOK_PER_BLK 32
#define NBLK        (NTOK / TOK_PER_BLK)
#define THREADS     512
#define XS_STRIDE   516   // 512+4 pad: lane bank offset 4 -> conflict-free LDS.128
#define SS_STRIDE   65
#define SMEM_BYTES  ((TOK_PER_BLK*XS_STRIDE + TOK_PER_BLK*SS_STRIDE + TOK_PER_BLK)*4)

// ============ packed weights (written by prep kernel each launch) ============
__device__ float4 g_WLR[16][32][5];   // {wl[9], wr[9], pad2} per (hidden ch, in ch)
__device__ float4 g_WJ [16][32][5];   // {wjl[9], wjr[9], pad2}
__device__ float4 g_WS4[16][64];      // {wl_s, wr_s, wjl_s, wjr_s}
__device__ float4 g_WB [16][32][6];   // per warp w, hidden ch c: {wout[2w][9], wout[2w+1][9], mvs2s[4w..4w+3], pad2}
__device__ float4 g_WBS[16][64][2];   // per warp w, scalar s

__global__ void gb_prep(
    const float* __restrict__ wl_mv, const float* __restrict__ wl_s,
    const float* __restrict__ wr_mv, const float* __restrict__ wr_s,
    const float* __restrict__ wjl_mv, const float* __restrict__ wjl_s,
    const float* __restrict__ wjr_mv, const float* __restrict__ wjr_s,
    const float* __restrict__ wo_mv, const float* __restrict__ wo_s2mv,
    const float* __restrict__ wo_mvs2s, const float* __restrict__ wo_s2s)
{
  int tid = blockIdx.x * blockDim.x + threadIdx.x;
  if (tid < 16*32){
    int c = tid >> 5, i = tid & 31;
    float t[20]; t[18]=0.f; t[19]=0.f;
    for (int b = 0; b < 9; ++b){ t[b] = wl_mv[(c*32+i)*9+b]; t[9+b] = wr_mv[(c*32+i)*9+b]; }
    for (int q = 0; q < 5; ++q) g_WLR[c][i][q] = make_float4(t[4*q],t[4*q+1],t[4*q+2],t[4*q+3]);
    for (int b = 0; b < 9; ++b){ t[b] = wjl_mv[(c*32+i)*9+b]; t[9+b] = wjr_mv[(c*32+i)*9+b]; }
    for (int q = 0; q < 5; ++q) g_WJ[c][i][q] = make_float4(t[4*q],t[4*q+1],t[4*q+2],t[4*q+3]);
    int w = c, c2 = i;
    float u[24]; u[22]=0.f; u[23]=0.f;
    for (int b = 0; b < 9; ++b){
      u[b]   = wo_mv[((2*w  )*32 + c2)*9 + b];
      u[9+b] = wo_mv[((2*w+1)*32 + c2)*9 + b];
    }
    for (int q = 0; q < 4; ++q) u[18+q] = wo_mvs2s[(4*w+q)*32 + c2];
    for (int q = 0; q < 6; ++q) g_WB[w][c2][q] = make_float4(u[4*q],u[4*q+1],u[4*q+2],u[4*q+3]);
  }
  if (tid < 16*64){
    int c = tid >> 6, s = tid & 63;
    g_WS4[c][s] = make_float4(wl_s[c*64+s], wr_s[c*64+s], wjl_s[c*64+s], wjr_s[c*64+s]);
    int w = c;
    g_WBS[w][s][0] = make_float4(wo_s2mv[(2*w)*64+s], wo_s2mv[(2*w+1)*64+s],
                                 wo_s2s[(4*w+0)*64+s], wo_s2s[(4*w+1)*64+s]);
    g_WBS[w][s][1] = make_float4(wo_s2s[(4*w+2)*64+s], wo_s2s[(4*w+3)*64+s], 0.f, 0.f);
  }
}

// ============ main kernel ============
__global__ void __launch_bounds__(THREADS, 1) gb_main(
    const float* __restrict__ mv, const float* __restrict__ refmv,
    const float* __restrict__ sc, float* __restrict__ out_mv, float* __restrict__ out_s)
{
  extern __shared__ float sm[];
  float* xs   = sm;                              // [32][516]: x, reused for hidden
  float* ss   = sm + TOK_PER_BLK*XS_STRIDE;      // [32][65]
  float* refs = ss + TOK_PER_BLK*SS_STRIDE;      // [32]
  const int tid = threadIdx.x;
  const long long t0 = (long long)blockIdx.x * TOK_PER_BLK;

  // stage x: coalesced gmem -> padded token-major smem
  {
    const float4* gx = (const float4*)(mv + t0*512);
    #pragma unroll
    for (int r = 0; r < 8; ++r){
      int g4 = r*THREADS + tid;
      int tok = g4 >> 7, f4 = g4 & 127;
      *(float4*)&xs[tok*XS_STRIDE + f4*4] = gx[g4];
    }
  }
  // stage scalars
  {
    float4 v = ((const float4*)(sc + t0*64))[tid];
    int tok = tid >> 4, s4 = tid & 15;
    float* p = &ss[tok*SS_STRIDE + s4*4];
    p[0]=v.x; p[1]=v.y; p[2]=v.z; p[3]=v.w;
  }
  if (tid < TOK_PER_BLK) refs[tid] = refmv[(t0+tid)*16 + 15];
  __syncthreads();

  const int w = tid >> 5, lane = tid & 31;
  const float* xrow = &xs[lane*XS_STRIDE];
  const long long gtok = t0 + lane;
  const float ref15 = refs[lane];

  // ---- scalar biases for the 4 first-stage equi-linears ----
  float bL=0.f, bR=0.f, bJL=0.f, bJR=0.f;
  #pragma unroll 8
  for (int s = 0; s < 64; ++s){
    float sv = ss[lane*SS_STRIDE + s];
    float4 wv = g_WS4[w][s];
    bL  = fmaf(wv.x, sv, bL);  bR  = fmaf(wv.y, sv, bR);
    bJL = fmaf(wv.z, sv, bJL); bJR = fmaf(wv.w, sv, bJR);
  }

  // ---- phase A (FUSED): load xi once, accumulate L, R, JL, JR together ----
  float ga[16], ja[16];
  {
    float L[16], R[16], JL[16], JR[16];
    #pragma unroll
    for (int j = 0; j < 16; ++j){ L[j]=0.f; R[j]=0.f; JL[j]=0.f; JR[j]=0.f; }
    L[0]=bL; R[0]=bR; JL[0]=bJL; JR[0]=bJR;
    #pragma unroll 2
    for (int i = 0; i < 32; ++i){
      float xi[16]; ldq<4>(xi, xrow + i*16);
      float wb[20];
      ldq<5>(wb, (const float*)g_WLR[w][i]);
      equi_step(L,  xi, wb);
      equi_step(R,  xi, wb+9);
      ldq<5>(wb, (const float*)g_WJ[w][i]);
      equi_step(JL, xi, wb);
      equi_step(JR, xi, wb+9);
    }
    #pragma unroll
    for (int j = 0; j < 16; ++j){ ga[j]=0.f; ja[j]=0.f; }
    gp_j<0>(ga, L, R);
    jn_j<0>(ja, JL, JR);
    #pragma unroll
    for (int j = 0; j < 16; ++j) ja[j] *= ref15;
  }

  // ---- write hidden back into xs (x is dead) ----
  __syncthreads();
  {
    float* hrow = &xs[lane*XS_STRIDE];
    #pragma unroll
    for (int q = 0; q < 4; ++q){
      *(float4*)(hrow +  w    *16 + 4*q) = make_float4(ga[4*q],ga[4*q+1],ga[4*q+2],ga[4*q+3]);
      *(float4*)(hrow + (16+w)*16 + 4*q) = make_float4(ja[4*q],ja[4*q+1],ja[4*q+2],ja[4*q+3]);
    }
  }
  __syncthreads();

  // ---- phase B: output equi-linear (ch 2w,2w+1) + out_s (ch 4w..4w+3) ----
  float b0=0.f, b1=0.f, os0=0.f, os1=0.f, os2=0.f, os3=0.f;
  #pragma unroll 8
  for (int s = 0; s < 64; ++s){
    float sv = ss[lane*SS_STRIDE + s];
    float4 u = g_WBS[w][s][0];
    float4 v = g_WBS[w][s][1];
    b0  = fmaf(u.x, sv, b0);  b1  = fmaf(u.y, sv, b1);
    os0 = fmaf(u.z, sv, os0); os1 = fmaf(u.w, sv, os1);
    os2 = fmaf(v.x, sv, os2); os3 = fmaf(v.y, sv, os3);
  }
  float A0[16], A1[16];
  #pragma unroll
  for (int j = 0; j < 16; ++j){ A0[j]=0.f; A1[j]=0.f; }
  A0[0]=b0; A1[0]=b1;
  const float* hrow = &xs[lane*XS_STRIDE];
  #pragma unroll 4
  for (int c = 0; c < 32; ++c){
    float hi[16]; ldq<4>(hi, hrow + c*16);
    float wb[24]; ldq<6>(wb, (const float*)g_WB[w][c]);
    equi_step(A0, hi, wb);
    equi_step(A1, hi, wb+9);
    os0 = fmaf(wb[18], hi[0], os0); os1 = fmaf(wb[19], hi[0], os1);
    os2 = fmaf(wb[20], hi[0], os2); os3 = fmaf(wb[21], hi[0], os3);
  }

  // ---- write outputs ----
  float* om = out_mv + (gtok*32 + 2*w)*16;
  #pragma unroll
  for (int q = 0; q < 4; ++q)
    ((float4*)om)[q]      = make_float4(A0[4*q],A0[4*q+1],A0[4*q+2],A0[4*q+3]);
  #pragma unroll
  for (int q = 0; q < 4; ++q)
    ((float4*)(om+16))[q] = make_float4(A1[4*q],A1[4*q+1],A1[4*q+2],A1[4*q+3]);
  *(float4*)(out_s + gtok*64 + 4*w) = make_float4(os0,os1,os2,os3);
}

// ============ launch ============
extern "C" void kernel_launch(void* const* d_in, const int* in_sizes, int n_in,
                              void* d_out, int out_size) {
  const float* mv    = (const float*)d_in[0];
  const float* refmv = (const float*)d_in[1];
  const float* sc    = (const float*)d_in[2];
  // d_in[3..5] = basis/gp/jn tables (folded at compile time)
  const float* wl_mv  = (const float*)d_in[6];
  const float* wl_s   = (const float*)d_in[7];
  const float* wr_mv  = (const float*)d_in[8];
  const float* wr_s   = (const float*)d_in[9];
  const float* wjl_mv = (const float*)d_in[10];
  const float* wjl_s  = (const float*)d_in[11];
  const float* wjr_mv = (const float*)d_in[12];
  const float* wjr_s  = (const float*)d_in[13];
  const float* wo_mv    = (const float*)d_in[14];
  const float* wo_s2mv  = (const float*)d_in[15];
  const float* wo_mvs2s = (const float*)d_in[16];
  const float* wo_s2s   = (const float*)d_in[17];

  float* out_mv = (float*)d_out;                       // (B,N,32,16)
  float* out_s  = out_mv + (long long)NTOK * 32 * 16;  // (B,N,64)

  gb_prep<<<2, 512>>>(wl_mv, wl_s, wr_mv, wr_s, wjl_mv, wjl_s, wjr_mv, wjr_s,
                      wo_mv, wo_s2mv, wo_mvs2s, wo_s2s);

  cudaFuncSetAttribute(gb_main, cudaFuncAttributeMaxDynamicSharedMemorySize, SMEM_BYTES);
  gb_main<<<NBLK, THREADS, SMEM_BYTES>>>(mv, refmv, sc, out_mv, out_s);
}